// round 15
// baseline (speedup 1.0000x reference)
#include <cuda_runtime.h>
#include <cuda_fp16.h>
#include <cstdint>

#define Bb 4
#define Cc 2048
#define Dd 1024
#define Kk 64
#define HK 512
#define HV 1024
#define Vd 128
#define Uu 256

#define STH 72                  // smem stride (halves), [m][k] tiles
#define TILEH (128 * STH)
#define VSTH 136                // smem stride (halves), [k][n] tiles
#define VTILEH (128 * VSTH)
#define BTILEH (64 * VSTH)      // 64-row [k][n] tile for k_projh

#define KE 0.18033688f          // 0.125 * log2(e)

// ---------------------------------------------------------------------------
// Scratch — natural layouts (R7-validated consumer addressing)
// ---------------------------------------------------------------------------
__device__ __align__(16) __half g_Xh[(size_t)Bb * Cc * Dd];       // 16 MB
__device__ __align__(16) __half g_Wq[(size_t)Dd * HK];
__device__ __align__(16) __half g_Wk[(size_t)Dd * HK];
__device__ __align__(16) __half g_Wv[(size_t)Dd * HV];
__device__ __align__(16) __half g_Pq[(size_t)Bb * Cc * HK];
__device__ __align__(16) __half g_Pk[(size_t)Bb * Cc * HK];
__device__ __align__(16) __half g_Pv[(size_t)Bb * Cc * HV];
__device__ __align__(16) float g_invD[Bb * 8 * Cc];   // holds -log2(D)

// ---------------------------------------------------------------------------
__device__ __forceinline__ uint32_t pack2(float x, float y) {
    __half2 h = __floats2half2_rn(x, y);
    return *reinterpret_cast<uint32_t*>(&h);
}

__device__ __forceinline__ float ex2(float x) {
    float y;
    asm("ex2.approx.f32 %0, %1;" : "=f"(y) : "f"(x));
    return y;
}

__device__ __forceinline__ void mma16(float* c, const uint32_t* a, const uint32_t* b) {
    asm volatile(
        "mma.sync.aligned.m16n8k16.row.col.f32.f16.f16.f32 "
        "{%0,%1,%2,%3}, {%4,%5,%6,%7}, {%8,%9}, {%0,%1,%2,%3};"
        : "+f"(c[0]), "+f"(c[1]), "+f"(c[2]), "+f"(c[3])
        : "r"(a[0]), "r"(a[1]), "r"(a[2]), "r"(a[3]), "r"(b[0]), "r"(b[1]));
}

__device__ __forceinline__ void ldm4(uint32_t* r, uint32_t addr) {
    asm volatile(
        "ldmatrix.sync.aligned.m8n8.x4.shared.b16 {%0,%1,%2,%3}, [%4];"
        : "=r"(r[0]), "=r"(r[1]), "=r"(r[2]), "=r"(r[3]) : "r"(addr));
}

__device__ __forceinline__ void ldm4t(uint32_t* r, uint32_t addr) {
    asm volatile(
        "ldmatrix.sync.aligned.m8n8.x4.trans.shared.b16 {%0,%1,%2,%3}, [%4];"
        : "=r"(r[0]), "=r"(r[1]), "=r"(r[2]), "=r"(r[3]) : "r"(addr));
}

__device__ __forceinline__ uint32_t s2u(const void* p) {
    return (uint32_t)__cvta_generic_to_shared(p);
}

__device__ __forceinline__ void cpa16(uint32_t d, const void* s) {
    asm volatile("cp.async.cg.shared.global [%0], [%1], 16;" :: "r"(d), "l"(s));
}
__device__ __forceinline__ void cp_commit() {
    asm volatile("cp.async.commit_group;");
}
template <int N> __device__ __forceinline__ void cp_wait() {
    asm volatile("cp.async.wait_group %0;" :: "n"(N));
}

// 64-deep k-tile warp mma, A [m][STH] via ldm4, B [n][SB] via ldm4.  (R7)
template <int SB>
__device__ __forceinline__ void warp_mma64(const __half* As, const __half* Bs,
                                           float acc[2][8][4],
                                           int wy, int wx, int lane) {
    const uint32_t ab = s2u(As), bb = s2u(Bs);
    const int arow = wy * 32 + (lane & 15);
    const int kA = (lane >> 4) << 3;
    const int brow = wx * 64 + (lane & 7) + ((lane >> 4) << 3);
    const int kB = ((lane >> 3) & 1) << 3;
#pragma unroll
    for (int ks = 0; ks < 4; ks++) {
        uint32_t a[2][4];
        ldm4(a[0], ab + (uint32_t)((arow * STH + ks * 16 + kA) * 2));
        ldm4(a[1], ab + (uint32_t)(((arow + 16) * STH + ks * 16 + kA) * 2));
#pragma unroll
        for (int j = 0; j < 4; j++) {
            uint32_t b[4];
            ldm4(b, bb + (uint32_t)(((brow + j * 16) * SB + ks * 16 + kB) * 2));
            mma16(acc[0][2 * j], a[0], b);
            mma16(acc[0][2 * j + 1], a[0], b + 2);
            mma16(acc[1][2 * j], a[1], b);
            mma16(acc[1][2 * j + 1], a[1], b + 2);
        }
    }
}

// 64-deep k-tile warp mma, A [m][STH] via ldm4, B natural [k][SB] via ldm4t.
template <int SB>
__device__ __forceinline__ void warp_mma64t(const __half* As, const __half* Bs,
                                            float acc[2][8][4],
                                            int wy, int wx, int lane) {
    const uint32_t ab = s2u(As), bb = s2u(Bs);
    const int arow = wy * 32 + (lane & 15);
    const int kA = (lane >> 4) << 3;
    const int vkrow = (lane & 7) + (((lane >> 3) & 1) << 3);
    const int vcol = (lane >> 4) << 3;
#pragma unroll
    for (int ks = 0; ks < 4; ks++) {
        uint32_t a[2][4];
        ldm4(a[0], ab + (uint32_t)((arow * STH + ks * 16 + kA) * 2));
        ldm4(a[1], ab + (uint32_t)(((arow + 16) * STH + ks * 16 + kA) * 2));
#pragma unroll
        for (int j = 0; j < 4; j++) {
            uint32_t b[4];
            ldm4t(b, bb + (uint32_t)(((ks * 16 + vkrow) * SB + wx * 64 + j * 16 + vcol) * 2));
            mma16(acc[0][2 * j], a[0], b);
            mma16(acc[0][2 * j + 1], a[0], b + 2);
            mma16(acc[1][2 * j], a[1], b);
            mma16(acc[1][2 * j + 1], a[1], b + 2);
        }
    }
}

// ---------------------------------------------------------------------------
// Merged convert kernel: all four fp32->fp16 conversions in one launch.
// ---------------------------------------------------------------------------
__global__ void k_cvt_all(const float* __restrict__ x, const float* __restrict__ mq,
                          const float* __restrict__ mk, const float* __restrict__ mv,
                          __half* __restrict__ xh, __half* __restrict__ wq,
                          __half* __restrict__ wk, __half* __restrict__ wv) {
    int bid = blockIdx.x;
    const float* src;
    __half* dst;
    size_t off;
    if (bid < 4096)      { src = x;  dst = xh; off = (size_t)bid * 2048; }
    else if (bid < 4352) { src = mq; dst = wq; off = (size_t)(bid - 4096) * 2048; }
    else if (bid < 4608) { src = mk; dst = wk; off = (size_t)(bid - 4352) * 2048; }
    else                 { src = mv; dst = wv; off = (size_t)(bid - 4608) * 2048; }
    size_t i = off + (size_t)threadIdx.x * 8;
    float4 a = *(const float4*)(src + i);
    float4 b = *(const float4*)(src + i + 4);
    *(uint4*)(dst + i) = make_uint4(pack2(a.x, a.y), pack2(a.z, a.w),
                                    pack2(b.x, b.y), pack2(b.z, b.w));
}

// ---------------------------------------------------------------------------
// Kernel: half GEMM  P[8192,N] = Xh @ Wh.  3-stage cp.async, 1 barrier/iter.
// ---------------------------------------------------------------------------
extern __shared__ __align__(16) __half dsm[];

__global__ __launch_bounds__(256, 2) void k_projh(const __half* __restrict__ X,
                                                  const __half* __restrict__ W,
                                                  __half* __restrict__ P, int N) {
    __half* Apb[3] = {dsm, dsm + TILEH, dsm + 2 * TILEH};
    __half* Bpb[3] = {dsm + 3 * TILEH, dsm + 3 * TILEH + BTILEH,
                      dsm + 3 * TILEH + 2 * BTILEH};
    const int tid = threadIdx.x, lane = tid & 31, wid = tid >> 5;
    const int wy = wid & 3, wx = wid >> 2;
    const int m0 = blockIdx.y * 128, n0 = blockIdx.x * 128;

    float acc[2][8][4];
#pragma unroll
    for (int i = 0; i < 2; i++)
#pragma unroll
        for (int j = 0; j < 8; j++)
#pragma unroll
            for (int c = 0; c < 4; c++) acc[i][j][c] = 0.f;

    auto fill = [&](int k0, __half* a, __half* bs) {
#pragma unroll
        for (int p = 0; p < 4; p++) {
            int id = tid + 256 * p, r = id >> 3, c = id & 7;
            cpa16(s2u(a + r * STH + c * 8), X + (size_t)(m0 + r) * Dd + k0 + c * 8);
        }
#pragma unroll
        for (int p = 0; p < 4; p++) {
            int id = tid + 256 * p, r = id >> 4, c = id & 15;
            cpa16(s2u(bs + r * VSTH + c * 8), W + (size_t)(k0 + r) * N + n0 + c * 8);
        }
    };

    fill(0, Apb[0], Bpb[0]);
    cp_commit();
    fill(64, Apb[1], Bpb[1]);
    cp_commit();

    const int NT = Dd / 64;
    for (int t = 0; t < NT; t++) {
        if (t + 1 < NT) cp_wait<1>(); else cp_wait<0>();
        __syncthreads();
        if (t + 2 < NT) {
            fill((t + 2) * 64, Apb[(t + 2) % 3], Bpb[(t + 2) % 3]);
            cp_commit();
        }
        warp_mma64t<VSTH>(Apb[t % 3], Bpb[t % 3], acc, wy, wx, lane);
    }

    const int tg = lane & 3, rr = lane >> 2;
#pragma unroll
    for (int mf = 0; mf < 2; mf++) {
        int m = m0 + wy * 32 + mf * 16 + rr;
#pragma unroll
        for (int nf = 0; nf < 8; nf++) {
            int n = n0 + wx * 64 + nf * 8 + tg * 2;
            *(uint32_t*)(P + (size_t)m * N + n) = pack2(acc[mf][nf][0], acc[mf][nf][1]);
            *(uint32_t*)(P + (size_t)(m + 8) * N + n) = pack2(acc[mf][nf][2], acc[mf][nf][3]);
        }
    }
}

// ---------------------------------------------------------------------------
// Kernel 2: g_invD[z][c2] = -log2(sum_q exp(S/8)).  K resident, Q 3-staged.
// ---------------------------------------------------------------------------
__global__ __launch_bounds__(256, 2) void k_sums() {
    __half* As = dsm;
    __half* Bs[3] = {dsm + TILEH, dsm + 2 * TILEH, dsm + 3 * TILEH};
    float* sD = (float*)(dsm + 4 * TILEH);
    const int tid = threadIdx.x, lane = tid & 31, wid = tid >> 5;
    const int wy = wid & 3, wx = wid >> 2;
    const int tg = lane & 3, rr = lane >> 2;
    const int z = blockIdx.y;
    const int c20 = blockIdx.x * 128;
    const __half* Kh = g_Pk + (size_t)z * Cc * Kk;
    const __half* Qh = g_Pq + (size_t)z * Cc * Kk;

    if (tid < 128) sD[tid] = 0.f;

    auto fillQ = [&](int q0, __half* dst) {
#pragma unroll
        for (int p = 0; p < 4; p++) {
            int id = tid + 256 * p, r = id >> 3, c = id & 7;
            cpa16(s2u(dst + r * STH + c * 8), Qh + (size_t)(q0 + r) * Kk + c * 8);
        }
    };

    // group 0: K tile + Q tile 0; group 1: Q tile 1
#pragma unroll
    for (int p = 0; p < 4; p++) {
        int id = tid + 256 * p, r = id >> 3, c = id & 7;
        cpa16(s2u(As + r * STH + c * 8), Kh + (size_t)(c20 + r) * Kk + c * 8);
    }
    fillQ(0, Bs[0]);
    cp_commit();
    fillQ(128, Bs[1]);
    cp_commit();

    float rs[2][2] = {{0.f, 0.f}, {0.f, 0.f}};
    const int NT = Cc / 128;
    for (int t = 0; t < NT; t++) {
        if (t + 1 < NT) cp_wait<1>(); else cp_wait<0>();
        __syncthreads();
        if (t + 2 < NT) {
            fillQ((t + 2) * 128, Bs[(t + 2) % 3]);
            cp_commit();
        }

        float acc[2][8][4];
#pragma unroll
        for (int i = 0; i < 2; i++)
#pragma unroll
            for (int j = 0; j < 8; j++)
#pragma unroll
                for (int c = 0; c < 4; c++) acc[i][j][c] = 0.f;
        warp_mma64<STH>(As, Bs[t % 3], acc, wy, wx, lane);
#pragma unroll
        for (int mf = 0; mf < 2; mf++)
#pragma unroll
            for (int nf = 0; nf < 8; nf++) {
                rs[mf][0] += __expf(acc[mf][nf][0] * 0.125f)
                           + __expf(acc[mf][nf][1] * 0.125f);
                rs[mf][1] += __expf(acc[mf][nf][2] * 0.125f)
                           + __expf(acc[mf][nf][3] * 0.125f);
            }
    }
#pragma unroll
    for (int mf = 0; mf < 2; mf++)
#pragma unroll
        for (int h2 = 0; h2 < 2; h2++) {
            float s = rs[mf][h2];
            s += __shfl_xor_sync(0xffffffffu, s, 1);
            s += __shfl_xor_sync(0xffffffffu, s, 2);
            if (tg == 0)
                atomicAdd(&sD[wy * 32 + mf * 16 + h2 * 8 + rr], s);
        }
    __syncthreads();
    if (tid < 128) g_invD[z * Cc + c20 + tid] = -__log2f(sD[tid]);
}

// ---------------------------------------------------------------------------
// Kernel 3: fused scores+softmax+PV.  3-stage K/V/iD pipeline, 1 barrier/iter.
// ---------------------------------------------------------------------------
__global__ __launch_bounds__(256, 1) void k_fused(float* __restrict__ out) {
    __half* Ks[3] = {dsm, dsm + TILEH, dsm + 2 * TILEH};
    __half* Vs[3] = {dsm + 3 * TILEH, dsm + 3 * TILEH + VTILEH,
                     dsm + 3 * TILEH + 2 * VTILEH};
    float* iDbase = (float*)(dsm + 3 * TILEH + 3 * VTILEH);
    float* iDs[3] = {iDbase, iDbase + 128, iDbase + 256};
    const int tid = threadIdx.x, lane = tid & 31, wid = tid >> 5;
    const int tg = lane & 3, rr = lane >> 2;
    const int w = blockIdx.x;
    const int b = w >> 6, h = (w >> 3) & 7, hp = w & 7, z = w >> 3;
    const __half* Qh = g_Pq + (size_t)z * Cc * Kk;
    const __half* Kh = g_Pk + (size_t)z * Cc * Kk;
    const __half* Bv = g_Pv + (size_t)b * Cc * HV + (size_t)hp * Uu * HV;
    const float* iD = g_invD + z * Cc;

    const int u1b = wid * 32 + rr;
    const __half* Qbase = Qh + (size_t)(8 * u1b + hp) * Kk;
    uint32_t Qa[2][4][4];
#pragma unroll
    for (int mf = 0; mf < 2; mf++) {
        const __half* Q0 = Qbase + (size_t)(mf * 128) * Kk;
        const __half* Q1 = Q0 + (size_t)64 * Kk;
#pragma unroll
        for (int ks = 0; ks < 4; ks++) {
            Qa[mf][ks][0] = *(const uint32_t*)(Q0 + ks * 16 + 2 * tg);
            Qa[mf][ks][1] = *(const uint32_t*)(Q1 + ks * 16 + 2 * tg);
            Qa[mf][ks][2] = *(const uint32_t*)(Q0 + ks * 16 + 8 + 2 * tg);
            Qa[mf][ks][3] = *(const uint32_t*)(Q1 + ks * 16 + 8 + 2 * tg);
        }
    }

    float of[2][16][4];
#pragma unroll
    for (int mf = 0; mf < 2; mf++)
#pragma unroll
        for (int j = 0; j < 16; j++)
#pragma unroll
            for (int c = 0; c < 4; c++) of[mf][j][c] = 0.f;

    auto fill = [&](int c20, __half* ks, __half* vs, float* ids) {
#pragma unroll
        for (int p = 0; p < 4; p++) {
            int id = tid + 256 * p, r = id >> 3, c = id & 7;
            cpa16(s2u(ks + r * STH + c * 8), Kh + (size_t)(c20 + r) * Kk + c * 8);
        }
#pragma unroll
        for (int p = 0; p < 8; p++) {
            int id = tid + 256 * p, r = id >> 4, c = id & 15;
            cpa16(s2u(vs + r * VSTH + c * 8), Bv + (size_t)(c20 + r) * Vd + c * 8);
        }
        if (tid < 32) cpa16(s2u(ids + tid * 4), iD + c20 + tid * 4);
    };

    fill(0, Ks[0], Vs[0], iDs[0]);
    cp_commit();
    fill(128, Ks[1], Vs[1], iDs[1]);
    cp_commit();

    const int brow = (lane & 7) + ((lane >> 4) << 3);
    const int kB = ((lane >> 3) & 1) << 3;
    const int vkrow = (lane & 7) + (((lane >> 3) & 1) << 3);
    const int vcol = (lane >> 4) << 3;

    const int NT = Cc / 128;
    for (int t = 0; t < NT; t++) {
        if (t + 1 < NT) cp_wait<1>(); else cp_wait<0>();
        __syncthreads();
        if (t + 2 < NT) {
            int s = (t + 2) % 3;
            fill((t + 2) * 128, Ks[s], Vs[s], iDs[s]);
            cp_commit();
        }

        const int sb = t % 3;
        const uint32_t ksb = s2u(Ks[sb]), vsb = s2u(Vs[sb]);
        const float* ids = iDs[sb];

#pragma unroll
        for (int qtr = 0; qtr < 4; qtr++) {
            float cf[2][4][4];
#pragma unroll
            for (int mf = 0; mf < 2; mf++)
#pragma unroll
                for (int n = 0; n < 4; n++)
#pragma unroll
                    for (int c = 0; c < 4; c++) cf[mf][n][c] = 0.f;
#pragma unroll
            for (int ks = 0; ks < 4; ks++) {
#pragma unroll
                for (int jj = 0; jj < 2; jj++) {
                    int j = qtr * 2 + jj;
                    uint32_t bfr[4];
                    ldm4(bfr, ksb + (uint32_t)(((j * 16 + brow) * STH + ks * 16 + kB) * 2));
                    mma16(cf[0][2 * jj], Qa[0][ks], bfr);
                    mma16(cf[0][2 * jj + 1], Qa[0][ks], bfr + 2);
                    mma16(cf[1][2 * jj], Qa[1][ks], bfr);
                    mma16(cf[1][2 * jj + 1], Qa[1][ks], bfr + 2);
                }
            }

            uint32_t ak[2][2][4];
#pragma unroll
            for (int mf = 0; mf < 2; mf++)
#pragma unroll
                for (int nfl = 0; nfl < 4; nfl++) {
                    int nfg = qtr * 4 + nfl;
                    float2 Lv = *(const float2*)(ids + nfg * 8 + 2 * tg);
                    float e0 = ex2(fmaf(cf[mf][nfl][0], KE, Lv.x));
                    float e1 = ex2(fmaf(cf[mf][nfl][1], KE, Lv.y));
                    float e2 = ex2(fmaf(cf[mf][nfl][2], KE, Lv.x));
                    float e3 = ex2(fmaf(cf[mf][nfl][3], KE, Lv.y));
                    ak[mf][nfl >> 1][(nfl & 1) * 2 + 0] = pack2(e0, e1);
                    ak[mf][nfl >> 1][(nfl & 1) * 2 + 1] = pack2(e2, e3);
                }

#pragma unroll
            for (int kk = 0; kk < 2; kk++) {
                int kb = qtr * 2 + kk;
#pragma unroll
                for (int j = 0; j < 8; j++) {
                    uint32_t bfr[4];
                    ldm4t(bfr, vsb + (uint32_t)(((kb * 16 + vkrow) * VSTH + j * 16 + vcol) * 2));
                    mma16(of[0][2 * j], ak[0][kk], bfr);
                    mma16(of[0][2 * j + 1], ak[0][kk], bfr + 2);
                    mma16(of[1][2 * j], ak[1][kk], bfr);
                    mma16(of[1][2 * j + 1], ak[1][kk], bfr + 2);
                }
            }
        }
    }

#pragma unroll
    for (int mf = 0; mf < 2; mf++) {
        int u1 = wid * 32 + mf * 16 + rr;
        float* g0 = out + ((size_t)b * Cc + h * Uu + u1) * HV + hp * Vd;
        float* g1 = g0 + (size_t)8 * HV;
#pragma unroll
        for (int df = 0; df < 16; df++) {
            int d = df * 8 + 2 * tg;
            *(float2*)(g0 + d) = make_float2(of[mf][df][0], of[mf][df][1]);
            *(float2*)(g1 + d) = make_float2(of[mf][df][2], of[mf][df][3]);
        }
    }
}

// ---------------------------------------------------------------------------
extern "C" void kernel_launch(void* const* d_in, const int* in_sizes, int n_in,
                              void* d_out, int out_size) {
    (void)in_sizes; (void)n_in; (void)out_size;
    const float* x  = (const float*)d_in[0];
    const float* Mq = (const float*)d_in[1];
    const float* Mk = (const float*)d_in[2];
    const float* Mv = (const float*)d_in[3];
    float* out = (float*)d_out;

    __half *pXh, *pWq, *pWk, *pWv, *pPq, *pPk, *pPv;
    cudaGetSymbolAddress((void**)&pXh, g_Xh);
    cudaGetSymbolAddress((void**)&pWq, g_Wq);
    cudaGetSymbolAddress((void**)&pWk, g_Wk);
    cudaGetSymbolAddress((void**)&pWv, g_Wv);
    cudaGetSymbolAddress((void**)&pPq, g_Pq);
    cudaGetSymbolAddress((void**)&pPk, g_Pk);
    cudaGetSymbolAddress((void**)&pPv, g_Pv);

    const int DSMP = (3 * TILEH + 3 * BTILEH) * sizeof(__half);          // 107520
    const int DSMS = 4 * TILEH * sizeof(__half) + 512;                   // 74240
    const int DSMF = (3 * TILEH + 3 * VTILEH) * sizeof(__half) + 1536;   // 161280
    static bool attr_done = false;
    if (!attr_done) {
        cudaFuncSetAttribute(k_projh, cudaFuncAttributeMaxDynamicSharedMemorySize, DSMP);
        cudaFuncSetAttribute(k_sums, cudaFuncAttributeMaxDynamicSharedMemorySize, DSMS);
        cudaFuncSetAttribute(k_fused, cudaFuncAttributeMaxDynamicSharedMemorySize, DSMF);
        attr_done = true;
    }

    // merged convert pass (1 launch)
    k_cvt_all<<<5120, 256>>>(x, Mq, Mk, Mv, pXh, pWq, pWk, pWv);

    // projections (natural layouts; consumers use flat-chunk addressing)
    k_projh<<<dim3(HK / 128, (Bb * Cc) / 128), 256, DSMP>>>(pXh, pWq, pPq, HK);
    k_projh<<<dim3(HK / 128, (Bb * Cc) / 128), 256, DSMP>>>(pXh, pWk, pPk, HK);
    k_projh<<<dim3(HV / 128, (Bb * Cc) / 128), 256, DSMP>>>(pXh, pWv, pPv, HV);

    k_sums<<<dim3(Cc / 128, Bb * 8), 256, DSMS>>>();
    k_fused<<<Bb * 8 * 8, 256, DSMF>>>(out);
}

// round 16
// speedup vs baseline: 1.0407x; 1.0407x over previous
#include <cuda_runtime.h>
#include <cuda_fp16.h>
#include <cstdint>

#define Bb 4
#define Cc 2048
#define Dd 1024
#define Kk 64
#define HK 512
#define HV 1024
#define Vd 128
#define Uu 256

#define STH 72                  // smem stride (halves), [m][k] tiles
#define TILEH (128 * STH)
#define VSTH 136                // smem stride (halves), [k][n] tiles
#define VTILEH (128 * VSTH)
#define BTILEH (64 * VSTH)      // 64-row [k][n] tile for projections

#define KE 0.18033688f          // 0.125 * log2(e)

// ---------------------------------------------------------------------------
// Scratch — natural layouts (R7-validated consumer addressing)
// ---------------------------------------------------------------------------
__device__ __align__(16) __half g_Xh[(size_t)Bb * Cc * Dd];       // 16 MB
__device__ __align__(16) __half g_Wq[(size_t)Dd * HK];
__device__ __align__(16) __half g_Wk[(size_t)Dd * HK];
__device__ __align__(16) __half g_Wv[(size_t)Dd * HV];
__device__ __align__(16) __half g_Pq[(size_t)Bb * Cc * HK];
__device__ __align__(16) __half g_Pk[(size_t)Bb * Cc * HK];
__device__ __align__(16) __half g_Pv[(size_t)Bb * Cc * HV];
__device__ __align__(16) __half g_invDh[Bb * 8 * Cc];   // 1/D as half

// ---------------------------------------------------------------------------
__device__ __forceinline__ uint32_t pack2(float x, float y) {
    __half2 h = __floats2half2_rn(x, y);
    return *reinterpret_cast<uint32_t*>(&h);
}

__device__ __forceinline__ uint32_t ex2h2(uint32_t x) {
    uint32_t y;
    asm("ex2.approx.f16x2 %0, %1;" : "=r"(y) : "r"(x));
    return y;
}

__device__ __forceinline__ uint32_t hmul2(uint32_t a, uint32_t b) {
    uint32_t y;
    asm("mul.f16x2 %0, %1, %2;" : "=r"(y) : "r"(a), "r"(b));
    return y;
}

__device__ __forceinline__ void mma16(float* c, const uint32_t* a, const uint32_t* b) {
    asm volatile(
        "mma.sync.aligned.m16n8k16.row.col.f32.f16.f16.f32 "
        "{%0,%1,%2,%3}, {%4,%5,%6,%7}, {%8,%9}, {%0,%1,%2,%3};"
        : "+f"(c[0]), "+f"(c[1]), "+f"(c[2]), "+f"(c[3])
        : "r"(a[0]), "r"(a[1]), "r"(a[2]), "r"(a[3]), "r"(b[0]), "r"(b[1]));
}

__device__ __forceinline__ void ldm4(uint32_t* r, uint32_t addr) {
    asm volatile(
        "ldmatrix.sync.aligned.m8n8.x4.shared.b16 {%0,%1,%2,%3}, [%4];"
        : "=r"(r[0]), "=r"(r[1]), "=r"(r[2]), "=r"(r[3]) : "r"(addr));
}

__device__ __forceinline__ void ldm4t(uint32_t* r, uint32_t addr) {
    asm volatile(
        "ldmatrix.sync.aligned.m8n8.x4.trans.shared.b16 {%0,%1,%2,%3}, [%4];"
        : "=r"(r[0]), "=r"(r[1]), "=r"(r[2]), "=r"(r[3]) : "r"(addr));
}

__device__ __forceinline__ uint32_t s2u(const void* p) {
    return (uint32_t)__cvta_generic_to_shared(p);
}

__device__ __forceinline__ void cpa16(uint32_t d, const void* s) {
    asm volatile("cp.async.cg.shared.global [%0], [%1], 16;" :: "r"(d), "l"(s));
}
__device__ __forceinline__ void cp_commit() {
    asm volatile("cp.async.commit_group;");
}
template <int N> __device__ __forceinline__ void cp_wait() {
    asm volatile("cp.async.wait_group %0;" :: "n"(N));
}

// 64-deep k-tile warp mma, A [m][STH] via ldm4, B [n][SB] via ldm4.
template <int SB>
__device__ __forceinline__ void warp_mma64(const __half* As, const __half* Bs,
                                           float acc[2][8][4],
                                           int wy, int wx, int lane) {
    const uint32_t ab = s2u(As), bb = s2u(Bs);
    const int arow = wy * 32 + (lane & 15);
    const int kA = (lane >> 4) << 3;
    const int brow = wx * 64 + (lane & 7) + ((lane >> 4) << 3);
    const int kB = ((lane >> 3) & 1) << 3;
#pragma unroll
    for (int ks = 0; ks < 4; ks++) {
        uint32_t a[2][4];
        ldm4(a[0], ab + (uint32_t)((arow * STH + ks * 16 + kA) * 2));
        ldm4(a[1], ab + (uint32_t)(((arow + 16) * STH + ks * 16 + kA) * 2));
#pragma unroll
        for (int j = 0; j < 4; j++) {
            uint32_t b[4];
            ldm4(b, bb + (uint32_t)(((brow + j * 16) * SB + ks * 16 + kB) * 2));
            mma16(acc[0][2 * j], a[0], b);
            mma16(acc[0][2 * j + 1], a[0], b + 2);
            mma16(acc[1][2 * j], a[1], b);
            mma16(acc[1][2 * j + 1], a[1], b + 2);
        }
    }
}

// 64-deep k-tile warp mma, A [m][STH] via ldm4, B natural [k][SB] via ldm4t.
template <int SB>
__device__ __forceinline__ void warp_mma64t(const __half* As, const __half* Bs,
                                            float acc[2][8][4],
                                            int wy, int wx, int lane) {
    const uint32_t ab = s2u(As), bb = s2u(Bs);
    const int arow = wy * 32 + (lane & 15);
    const int kA = (lane >> 4) << 3;
    const int vkrow = (lane & 7) + (((lane >> 3) & 1) << 3);
    const int vcol = (lane >> 4) << 3;
#pragma unroll
    for (int ks = 0; ks < 4; ks++) {
        uint32_t a[2][4];
        ldm4(a[0], ab + (uint32_t)((arow * STH + ks * 16 + kA) * 2));
        ldm4(a[1], ab + (uint32_t)(((arow + 16) * STH + ks * 16 + kA) * 2));
#pragma unroll
        for (int j = 0; j < 4; j++) {
            uint32_t b[4];
            ldm4t(b, bb + (uint32_t)(((ks * 16 + vkrow) * SB + wx * 64 + j * 16 + vcol) * 2));
            mma16(acc[0][2 * j], a[0], b);
            mma16(acc[0][2 * j + 1], a[0], b + 2);
            mma16(acc[1][2 * j], a[1], b);
            mma16(acc[1][2 * j + 1], a[1], b + 2);
        }
    }
}

// ---------------------------------------------------------------------------
// Merged convert kernel
// ---------------------------------------------------------------------------
__global__ void k_cvt_all(const float* __restrict__ x, const float* __restrict__ mq,
                          const float* __restrict__ mk, const float* __restrict__ mv,
                          __half* __restrict__ xh, __half* __restrict__ wq,
                          __half* __restrict__ wk, __half* __restrict__ wv) {
    int bid = blockIdx.x;
    const float* src;
    __half* dst;
    size_t off;
    if (bid < 4096)      { src = x;  dst = xh; off = (size_t)bid * 2048; }
    else if (bid < 4352) { src = mq; dst = wq; off = (size_t)(bid - 4096) * 2048; }
    else if (bid < 4608) { src = mk; dst = wk; off = (size_t)(bid - 4352) * 2048; }
    else                 { src = mv; dst = wv; off = (size_t)(bid - 4608) * 2048; }
    size_t i = off + (size_t)threadIdx.x * 8;
    float4 a = *(const float4*)(src + i);
    float4 b = *(const float4*)(src + i + 4);
    *(uint4*)(dst + i) = make_uint4(pack2(a.x, a.y), pack2(a.z, a.w),
                                    pack2(b.x, b.y), pack2(b.z, b.w));
}

// ---------------------------------------------------------------------------
// Merged projection kernel: one launch covers Q, K, V GEMMs.
// blockIdx.x: 0-3 -> Q, 4-7 -> K, 8-15 -> V.  (R14 2-stage body)
// ---------------------------------------------------------------------------
extern __shared__ __align__(16) __half dsm[];

__global__ __launch_bounds__(256) void k_proj3(const __half* __restrict__ X,
                                               const __half* __restrict__ Wq,
                                               const __half* __restrict__ Wk,
                                               const __half* __restrict__ Wv,
                                               __half* __restrict__ Pq,
                                               __half* __restrict__ Pk,
                                               __half* __restrict__ Pv) {
    const int bx = blockIdx.x;
    const __half* W;
    __half* P;
    int N, n0;
    if (bx < 4)      { W = Wq; P = Pq; N = HK; n0 = bx * 128; }
    else if (bx < 8) { W = Wk; P = Pk; N = HK; n0 = (bx - 4) * 128; }
    else             { W = Wv; P = Pv; N = HV; n0 = (bx - 8) * 128; }

    __half* Apb[2] = {dsm, dsm + TILEH};
    __half* Bpb[2] = {dsm + 2 * TILEH, dsm + 2 * TILEH + BTILEH};
    const int tid = threadIdx.x, lane = tid & 31, wid = tid >> 5;
    const int wy = wid & 3, wx = wid >> 2;
    const int m0 = blockIdx.y * 128;

    float acc[2][8][4];
#pragma unroll
    for (int i = 0; i < 2; i++)
#pragma unroll
        for (int j = 0; j < 8; j++)
#pragma unroll
            for (int c = 0; c < 4; c++) acc[i][j][c] = 0.f;

    auto fill = [&](int k0, __half* a, __half* bs) {
#pragma unroll
        for (int p = 0; p < 4; p++) {
            int id = tid + 256 * p, r = id >> 3, c = id & 7;
            cpa16(s2u(a + r * STH + c * 8), X + (size_t)(m0 + r) * Dd + k0 + c * 8);
        }
#pragma unroll
        for (int p = 0; p < 4; p++) {
            int id = tid + 256 * p, r = id >> 4, c = id & 15;
            cpa16(s2u(bs + r * VSTH + c * 8), W + (size_t)(k0 + r) * N + n0 + c * 8);
        }
    };

    fill(0, Apb[0], Bpb[0]);
    cp_commit();

    const int NT = Dd / 64;
    for (int t = 0; t < NT; t++) {
        if (t + 1 < NT) {
            fill((t + 1) * 64, Apb[(t + 1) & 1], Bpb[(t + 1) & 1]);
            cp_commit();
            cp_wait<1>();
        } else {
            cp_wait<0>();
        }
        __syncthreads();
        warp_mma64t<VSTH>(Apb[t & 1], Bpb[t & 1], acc, wy, wx, lane);
        __syncthreads();
    }

    const int tg = lane & 3, rr = lane >> 2;
#pragma unroll
    for (int mf = 0; mf < 2; mf++) {
        int m = m0 + wy * 32 + mf * 16 + rr;
#pragma unroll
        for (int nf = 0; nf < 8; nf++) {
            int n = n0 + wx * 64 + nf * 8 + tg * 2;
            *(uint32_t*)(P + (size_t)m * N + n) = pack2(acc[mf][nf][0], acc[mf][nf][1]);
            *(uint32_t*)(P + (size_t)(m + 8) * N + n) = pack2(acc[mf][nf][2], acc[mf][nf][3]);
        }
    }
}

// ---------------------------------------------------------------------------
// Kernel 2: g_invDh[z][c2] = half(1 / sum_q exp(S/8)).  f16x2 ex2 path.
// ---------------------------------------------------------------------------
__global__ __launch_bounds__(256, 2) void k_sums() {
    __half* As = dsm;
    __half* Bs[2] = {dsm + TILEH, dsm + 2 * TILEH};
    float* sD = (float*)(dsm + 3 * TILEH);
    const int tid = threadIdx.x, lane = tid & 31, wid = tid >> 5;
    const int wy = wid & 3, wx = wid >> 2;
    const int tg = lane & 3, rr = lane >> 2;
    const int z = blockIdx.y;
    const int c20 = blockIdx.x * 128;
    const __half* Kh = g_Pk + (size_t)z * Cc * Kk;
    const __half* Qh = g_Pq + (size_t)z * Cc * Kk;

    if (tid < 128) sD[tid] = 0.f;

#pragma unroll
    for (int p = 0; p < 4; p++) {
        int id = tid + 256 * p, r = id >> 3, c = id & 7;
        cpa16(s2u(As + r * STH + c * 8), Kh + (size_t)(c20 + r) * Kk + c * 8);
        cpa16(s2u(Bs[0] + r * STH + c * 8), Qh + (size_t)r * Kk + c * 8);
    }
    cp_commit();

    float rs[2][2] = {{0.f, 0.f}, {0.f, 0.f}};
    const int NT = Cc / 128;
    for (int t = 0; t < NT; t++) {
        __syncthreads();
        if (t + 1 < NT) {
            const __half* src = Qh + (size_t)(t + 1) * 128 * Kk;
            __half* dst = Bs[(t + 1) & 1];
#pragma unroll
            for (int p = 0; p < 4; p++) {
                int id = tid + 256 * p, r = id >> 3, c = id & 7;
                cpa16(s2u(dst + r * STH + c * 8), src + (size_t)r * Kk + c * 8);
            }
            cp_commit();
            cp_wait<1>();
        } else {
            cp_wait<0>();
        }
        __syncthreads();

        float acc[2][8][4];
#pragma unroll
        for (int i = 0; i < 2; i++)
#pragma unroll
            for (int j = 0; j < 8; j++)
#pragma unroll
                for (int c = 0; c < 4; c++) acc[i][j][c] = 0.f;
        warp_mma64<STH>(As, Bs[t & 1], acc, wy, wx, lane);
#pragma unroll
        for (int mf = 0; mf < 2; mf++)
#pragma unroll
            for (int nf = 0; nf < 8; nf++) {
                uint32_t e0 = ex2h2(pack2(acc[mf][nf][0] * KE, acc[mf][nf][1] * KE));
                uint32_t e1 = ex2h2(pack2(acc[mf][nf][2] * KE, acc[mf][nf][3] * KE));
                float2 f0 = __half22float2(*(__half2*)&e0);
                float2 f1 = __half22float2(*(__half2*)&e1);
                rs[mf][0] += f0.x + f0.y;
                rs[mf][1] += f1.x + f1.y;
            }
    }
#pragma unroll
    for (int mf = 0; mf < 2; mf++)
#pragma unroll
        for (int h2 = 0; h2 < 2; h2++) {
            float s = rs[mf][h2];
            s += __shfl_xor_sync(0xffffffffu, s, 1);
            s += __shfl_xor_sync(0xffffffffu, s, 2);
            if (tg == 0)
                atomicAdd(&sD[wy * 32 + mf * 16 + h2 * 8 + rr], s);
        }
    __syncthreads();
    if (tid < 128)
        g_invDh[z * Cc + c20 + tid] = __float2half_rn(1.0f / sD[tid]);
}

// ---------------------------------------------------------------------------
// Kernel 3: fused scores+softmax+PV (R14 shape).  e = ex2.f16x2(s*KE) then
// half invD multiply — MUFU halved, small exponent args for accuracy.
// ---------------------------------------------------------------------------
__global__ __launch_bounds__(256, 1) void k_fused(float* __restrict__ out) {
    __half* Ks[2] = {dsm, dsm + TILEH};
    __half* Vs[2] = {dsm + 2 * TILEH, dsm + 2 * TILEH + VTILEH};
    __half* iDbase = dsm + 2 * TILEH + 2 * VTILEH;
    __half* iDs[2] = {iDbase, iDbase + 128};
    const int tid = threadIdx.x, lane = tid & 31, wid = tid >> 5;
    const int tg = lane & 3, rr = lane >> 2;
    const int w = blockIdx.x;
    const int b = w >> 6, h = (w >> 3) & 7, hp = w & 7, z = w >> 3;
    const __half* Qh = g_Pq + (size_t)z * Cc * Kk;
    const __half* Kh = g_Pk + (size_t)z * Cc * Kk;
    const __half* Bv = g_Pv + (size_t)b * Cc * HV + (size_t)hp * Uu * HV;
    const __half* iDh = g_invDh + z * Cc;

    const int u1b = wid * 32 + rr;
    const __half* Qbase = Qh + (size_t)(8 * u1b + hp) * Kk;
    uint32_t Qa[2][4][4];
#pragma unroll
    for (int mf = 0; mf < 2; mf++) {
        const __half* Q0 = Qbase + (size_t)(mf * 128) * Kk;
        const __half* Q1 = Q0 + (size_t)64 * Kk;
#pragma unroll
        for (int ks = 0; ks < 4; ks++) {
            Qa[mf][ks][0] = *(const uint32_t*)(Q0 + ks * 16 + 2 * tg);
            Qa[mf][ks][1] = *(const uint32_t*)(Q1 + ks * 16 + 2 * tg);
            Qa[mf][ks][2] = *(const uint32_t*)(Q0 + ks * 16 + 8 + 2 * tg);
            Qa[mf][ks][3] = *(const uint32_t*)(Q1 + ks * 16 + 8 + 2 * tg);
        }
    }

    float of[2][16][4];
#pragma unroll
    for (int mf = 0; mf < 2; mf++)
#pragma unroll
        for (int j = 0; j < 16; j++)
#pragma unroll
            for (int c = 0; c < 4; c++) of[mf][j][c] = 0.f;

    auto fill = [&](int c20, __half* ks, __half* vs, __half* ids) {
#pragma unroll
        for (int p = 0; p < 4; p++) {
            int id = tid + 256 * p, r = id >> 3, c = id & 7;
            cpa16(s2u(ks + r * STH + c * 8), Kh + (size_t)(c20 + r) * Kk + c * 8);
        }
#pragma unroll
        for (int p = 0; p < 8; p++) {
            int id = tid + 256 * p, r = id >> 4, c = id & 15;
            cpa16(s2u(vs + r * VSTH + c * 8), Bv + (size_t)(c20 + r) * Vd + c * 8);
        }
        if (tid < 16) cpa16(s2u(ids + tid * 8), iDh + c20 + tid * 8);
    };

    fill(0, Ks[0], Vs[0], iDs[0]);
    cp_commit();

    const int brow = (lane & 7) + ((lane >> 4) << 3);
    const int kB = ((lane >> 3) & 1) << 3;
    const int vkrow = (lane & 7) + (((lane >> 3) & 1) << 3);
    const int vcol = (lane >> 4) << 3;

    const int NT = Cc / 128;
    for (int t = 0; t < NT; t++) {
        __syncthreads();
        if (t + 1 < NT) {
            fill((t + 1) * 128, Ks[(t + 1) & 1], Vs[(t + 1) & 1], iDs[(t + 1) & 1]);
            cp_commit();
            cp_wait<1>();
        } else {
            cp_wait<0>();
        }
        __syncthreads();

        const uint32_t ksb = s2u(Ks[t & 1]), vsb = s2u(Vs[t & 1]);
        const __half* ids = iDs[t & 1];

#pragma unroll
        for (int qtr = 0; qtr < 4; qtr++) {
            float cf[2][4][4];
#pragma unroll
            for (int mf = 0; mf < 2; mf++)
#pragma unroll
                for (int n = 0; n < 4; n++)
#pragma unroll
                    for (int c = 0; c < 4; c++) cf[mf][n][c] = 0.f;
#pragma unroll
            for (int ks = 0; ks < 4; ks++) {
#pragma unroll
                for (int jj = 0; jj < 2; jj++) {
                    int j = qtr * 2 + jj;
                    uint32_t bfr[4];
                    ldm4(bfr, ksb + (uint32_t)(((j * 16 + brow) * STH + ks * 16 + kB) * 2));
                    mma16(cf[0][2 * jj], Qa[0][ks], bfr);
                    mma16(cf[0][2 * jj + 1], Qa[0][ks], bfr + 2);
                    mma16(cf[1][2 * jj], Qa[1][ks], bfr);
                    mma16(cf[1][2 * jj + 1], Qa[1][ks], bfr + 2);
                }
            }

            uint32_t ak[2][2][4];
#pragma unroll
            for (int mf = 0; mf < 2; mf++)
#pragma unroll
                for (int nfl = 0; nfl < 4; nfl++) {
                    int nfg = qtr * 4 + nfl;
                    uint32_t idh = *(const uint32_t*)(ids + nfg * 8 + 2 * tg);
                    uint32_t e0 = ex2h2(pack2(cf[mf][nfl][0] * KE, cf[mf][nfl][1] * KE));
                    uint32_t e1 = ex2h2(pack2(cf[mf][nfl][2] * KE, cf[mf][nfl][3] * KE));
                    ak[mf][nfl >> 1][(nfl & 1) * 2 + 0] = hmul2(e0, idh);
                    ak[mf][nfl >> 1][(nfl & 1) * 2 + 1] = hmul2(e1, idh);
                }

#pragma unroll
            for (int kk = 0; kk < 2; kk++) {
                int kb = qtr * 2 + kk;
#pragma unroll
                for (int j = 0; j < 8; j++) {
                    uint32_t bfr[4];
                    ldm4t(bfr, vsb + (uint32_t)(((kb * 16 + vkrow) * VSTH + j * 16 + vcol) * 2));
                    mma16(of[0][2 * j], ak[0][kk], bfr);
                    mma16(of[0][2 * j + 1], ak[0][kk], bfr + 2);
                    mma16(of[1][2 * j], ak[1][kk], bfr);
                    mma16(of[1][2 * j + 1], ak[1][kk], bfr + 2);
                }
            }
        }
    }

#pragma unroll
    for (int mf = 0; mf < 2; mf++) {
        int u1 = wid * 32 + mf * 16 + rr;
        float* g0 = out + ((size_t)b * Cc + h * Uu + u1) * HV + hp * Vd;
        float* g1 = g0 + (size_t)8 * HV;
#pragma unroll
        for (int df = 0; df < 16; df++) {
            int d = df * 8 + 2 * tg;
            *(float2*)(g0 + d) = make_float2(of[mf][df][0], of[mf][df][1]);
            *(float2*)(g1 + d) = make_float2(of[mf][df][2], of[mf][df][3]);
        }
    }
}

// ---------------------------------------------------------------------------
extern "C" void kernel_launch(void* const* d_in, const int* in_sizes, int n_in,
                              void* d_out, int out_size) {
    (void)in_sizes; (void)n_in; (void)out_size;
    const float* x  = (const float*)d_in[0];
    const float* Mq = (const float*)d_in[1];
    const float* Mk = (const float*)d_in[2];
    const float* Mv = (const float*)d_in[3];
    float* out = (float*)d_out;

    __half *pXh, *pWq, *pWk, *pWv, *pPq, *pPk, *pPv;
    cudaGetSymbolAddress((void**)&pXh, g_Xh);
    cudaGetSymbolAddress((void**)&pWq, g_Wq);
    cudaGetSymbolAddress((void**)&pWk, g_Wk);
    cudaGetSymbolAddress((void**)&pWv, g_Wv);
    cudaGetSymbolAddress((void**)&pPq, g_Pq);
    cudaGetSymbolAddress((void**)&pPk, g_Pk);
    cudaGetSymbolAddress((void**)&pPv, g_Pv);

    const int DSMP = (2 * TILEH + 2 * BTILEH) * sizeof(__half);          // 71680
    const int DSMS = 3 * TILEH * sizeof(__half) + 512;                   // 55808
    const int DSMF = (2 * TILEH + 2 * VTILEH) * sizeof(__half) + 1024;   // 107520
    static bool attr_done = false;
    if (!attr_done) {
        cudaFuncSetAttribute(k_proj3, cudaFuncAttributeMaxDynamicSharedMemorySize, DSMP);
        cudaFuncSetAttribute(k_sums, cudaFuncAttributeMaxDynamicSharedMemorySize, DSMS);
        cudaFuncSetAttribute(k_fused, cudaFuncAttributeMaxDynamicSharedMemorySize, DSMF);
        attr_done = true;
    }

    // merged convert pass (1 launch)
    k_cvt_all<<<5120, 256>>>(x, Mq, Mk, Mv, pXh, pWq, pWk, pWv);

    // merged projection pass (1 launch: Q, K, V)
    k_proj3<<<dim3(16, (Bb * Cc) / 128), 256, DSMP>>>(pXh, pWq, pWk, pWv,
                                                      pPq, pPk, pPv);

    k_sums<<<dim3(Cc / 128, Bb * 8), 256, DSMS>>>();
    k_fused<<<Bb * 8 * 8, 256, DSMF>>>(out);
}

// round 17
// speedup vs baseline: 1.0488x; 1.0077x over previous
#include <cuda_runtime.h>
#include <cuda_fp16.h>
#include <cstdint>

#define Bb 4
#define Cc 2048
#define Dd 1024
#define Kk 64
#define HK 512
#define HV 1024
#define Vd 128
#define Uu 256

#define STH 72                  // smem stride (halves), [m][k] tiles
#define TILEH (128 * STH)
#define VSTH 136                // smem stride (halves), [k][n] tiles
#define VTILEH (128 * VSTH)
#define BTILEH (64 * VSTH)      // 64-row [k][n] tile for projections

#define KE 0.18033688f          // 0.125 * log2(e)

// ---------------------------------------------------------------------------
// Scratch — natural layouts (R7-validated consumer addressing)
// ---------------------------------------------------------------------------
__device__ __align__(16) __half g_Xh[(size_t)Bb * Cc * Dd];       // 16 MB
__device__ __align__(16) __half g_Wq[(size_t)Dd * HK];
__device__ __align__(16) __half g_Wk[(size_t)Dd * HK];
__device__ __align__(16) __half g_Wv[(size_t)Dd * HV];
__device__ __align__(16) __half g_Pq[(size_t)Bb * Cc * HK];
__device__ __align__(16) __half g_Pk[(size_t)Bb * Cc * HK];
__device__ __align__(16) __half g_Pv[(size_t)Bb * Cc * HV];
__device__ __align__(16) __half g_invDh[Bb * 8 * Cc];   // 1/D as half

// ---------------------------------------------------------------------------
__device__ __forceinline__ uint32_t pack2(float x, float y) {
    __half2 h = __floats2half2_rn(x, y);
    return *reinterpret_cast<uint32_t*>(&h);
}

__device__ __forceinline__ uint32_t ex2h2(uint32_t x) {
    uint32_t y;
    asm("ex2.approx.f16x2 %0, %1;" : "=r"(y) : "r"(x));
    return y;
}

__device__ __forceinline__ uint32_t hmul2(uint32_t a, uint32_t b) {
    uint32_t y;
    asm("mul.f16x2 %0, %1, %2;" : "=r"(y) : "r"(a), "r"(b));
    return y;
}

__device__ __forceinline__ void mma16(float* c, const uint32_t* a, const uint32_t* b) {
    asm volatile(
        "mma.sync.aligned.m16n8k16.row.col.f32.f16.f16.f32 "
        "{%0,%1,%2,%3}, {%4,%5,%6,%7}, {%8,%9}, {%0,%1,%2,%3};"
        : "+f"(c[0]), "+f"(c[1]), "+f"(c[2]), "+f"(c[3])
        : "r"(a[0]), "r"(a[1]), "r"(a[2]), "r"(a[3]), "r"(b[0]), "r"(b[1]));
}

__device__ __forceinline__ void ldm4(uint32_t* r, uint32_t addr) {
    asm volatile(
        "ldmatrix.sync.aligned.m8n8.x4.shared.b16 {%0,%1,%2,%3}, [%4];"
        : "=r"(r[0]), "=r"(r[1]), "=r"(r[2]), "=r"(r[3]) : "r"(addr));
}

__device__ __forceinline__ void ldm4t(uint32_t* r, uint32_t addr) {
    asm volatile(
        "ldmatrix.sync.aligned.m8n8.x4.trans.shared.b16 {%0,%1,%2,%3}, [%4];"
        : "=r"(r[0]), "=r"(r[1]), "=r"(r[2]), "=r"(r[3]) : "r"(addr));
}

__device__ __forceinline__ uint32_t s2u(const void* p) {
    return (uint32_t)__cvta_generic_to_shared(p);
}

__device__ __forceinline__ void cpa16(uint32_t d, const void* s) {
    asm volatile("cp.async.cg.shared.global [%0], [%1], 16;" :: "r"(d), "l"(s));
}
__device__ __forceinline__ void cp_commit() {
    asm volatile("cp.async.commit_group;");
}
template <int N> __device__ __forceinline__ void cp_wait() {
    asm volatile("cp.async.wait_group %0;" :: "n"(N));
}

// 64-deep k-tile warp mma, A [m][STH] via ldm4, B [n][SB] via ldm4.
template <int SB>
__device__ __forceinline__ void warp_mma64(const __half* As, const __half* Bs,
                                           float acc[2][8][4],
                                           int wy, int wx, int lane) {
    const uint32_t ab = s2u(As), bb = s2u(Bs);
    const int arow = wy * 32 + (lane & 15);
    const int kA = (lane >> 4) << 3;
    const int brow = wx * 64 + (lane & 7) + ((lane >> 4) << 3);
    const int kB = ((lane >> 3) & 1) << 3;
#pragma unroll
    for (int ks = 0; ks < 4; ks++) {
        uint32_t a[2][4];
        ldm4(a[0], ab + (uint32_t)((arow * STH + ks * 16 + kA) * 2));
        ldm4(a[1], ab + (uint32_t)(((arow + 16) * STH + ks * 16 + kA) * 2));
#pragma unroll
        for (int j = 0; j < 4; j++) {
            uint32_t b[4];
            ldm4(b, bb + (uint32_t)(((brow + j * 16) * SB + ks * 16 + kB) * 2));
            mma16(acc[0][2 * j], a[0], b);
            mma16(acc[0][2 * j + 1], a[0], b + 2);
            mma16(acc[1][2 * j], a[1], b);
            mma16(acc[1][2 * j + 1], a[1], b + 2);
        }
    }
}

// 64-deep k-tile warp mma, A [m][STH] via ldm4, B natural [k][SB] via ldm4t.
template <int SB>
__device__ __forceinline__ void warp_mma64t(const __half* As, const __half* Bs,
                                            float acc[2][8][4],
                                            int wy, int wx, int lane) {
    const uint32_t ab = s2u(As), bb = s2u(Bs);
    const int arow = wy * 32 + (lane & 15);
    const int kA = (lane >> 4) << 3;
    const int vkrow = (lane & 7) + (((lane >> 3) & 1) << 3);
    const int vcol = (lane >> 4) << 3;
#pragma unroll
    for (int ks = 0; ks < 4; ks++) {
        uint32_t a[2][4];
        ldm4(a[0], ab + (uint32_t)((arow * STH + ks * 16 + kA) * 2));
        ldm4(a[1], ab + (uint32_t)(((arow + 16) * STH + ks * 16 + kA) * 2));
#pragma unroll
        for (int j = 0; j < 4; j++) {
            uint32_t b[4];
            ldm4t(b, bb + (uint32_t)(((ks * 16 + vkrow) * SB + wx * 64 + j * 16 + vcol) * 2));
            mma16(acc[0][2 * j], a[0], b);
            mma16(acc[0][2 * j + 1], a[0], b + 2);
            mma16(acc[1][2 * j], a[1], b);
            mma16(acc[1][2 * j + 1], a[1], b + 2);
        }
    }
}

// ---------------------------------------------------------------------------
// Merged convert kernel
// ---------------------------------------------------------------------------
__global__ void k_cvt_all(const float* __restrict__ x, const float* __restrict__ mq,
                          const float* __restrict__ mk, const float* __restrict__ mv,
                          __half* __restrict__ xh, __half* __restrict__ wq,
                          __half* __restrict__ wk, __half* __restrict__ wv) {
    int bid = blockIdx.x;
    const float* src;
    __half* dst;
    size_t off;
    if (bid < 4096)      { src = x;  dst = xh; off = (size_t)bid * 2048; }
    else if (bid < 4352) { src = mq; dst = wq; off = (size_t)(bid - 4096) * 2048; }
    else if (bid < 4608) { src = mk; dst = wk; off = (size_t)(bid - 4352) * 2048; }
    else                 { src = mv; dst = wv; off = (size_t)(bid - 4608) * 2048; }
    size_t i = off + (size_t)threadIdx.x * 8;
    float4 a = *(const float4*)(src + i);
    float4 b = *(const float4*)(src + i + 4);
    *(uint4*)(dst + i) = make_uint4(pack2(a.x, a.y), pack2(a.z, a.w),
                                    pack2(b.x, b.y), pack2(b.z, b.w));
}

// ---------------------------------------------------------------------------
// Merged projection kernel: one launch covers Q, K, V GEMMs.
// ---------------------------------------------------------------------------
extern __shared__ __align__(16) __half dsm[];

__global__ __launch_bounds__(256) void k_proj3(const __half* __restrict__ X,
                                               const __half* __restrict__ Wq,
                                               const __half* __restrict__ Wk,
                                               const __half* __restrict__ Wv,
                                               __half* __restrict__ Pq,
                                               __half* __restrict__ Pk,
                                               __half* __restrict__ Pv) {
    const int bx = blockIdx.x;
    const __half* W;
    __half* P;
    int N, n0;
    if (bx < 4)      { W = Wq; P = Pq; N = HK; n0 = bx * 128; }
    else if (bx < 8) { W = Wk; P = Pk; N = HK; n0 = (bx - 4) * 128; }
    else             { W = Wv; P = Pv; N = HV; n0 = (bx - 8) * 128; }

    __half* Apb[2] = {dsm, dsm + TILEH};
    __half* Bpb[2] = {dsm + 2 * TILEH, dsm + 2 * TILEH + BTILEH};
    const int tid = threadIdx.x, lane = tid & 31, wid = tid >> 5;
    const int wy = wid & 3, wx = wid >> 2;
    const int m0 = blockIdx.y * 128;

    float acc[2][8][4];
#pragma unroll
    for (int i = 0; i < 2; i++)
#pragma unroll
        for (int j = 0; j < 8; j++)
#pragma unroll
            for (int c = 0; c < 4; c++) acc[i][j][c] = 0.f;

    auto fill = [&](int k0, __half* a, __half* bs) {
#pragma unroll
        for (int p = 0; p < 4; p++) {
            int id = tid + 256 * p, r = id >> 3, c = id & 7;
            cpa16(s2u(a + r * STH + c * 8), X + (size_t)(m0 + r) * Dd + k0 + c * 8);
        }
#pragma unroll
        for (int p = 0; p < 4; p++) {
            int id = tid + 256 * p, r = id >> 4, c = id & 15;
            cpa16(s2u(bs + r * VSTH + c * 8), W + (size_t)(k0 + r) * N + n0 + c * 8);
        }
    };

    fill(0, Apb[0], Bpb[0]);
    cp_commit();

    const int NT = Dd / 64;
    for (int t = 0; t < NT; t++) {
        if (t + 1 < NT) {
            fill((t + 1) * 64, Apb[(t + 1) & 1], Bpb[(t + 1) & 1]);
            cp_commit();
            cp_wait<1>();
        } else {
            cp_wait<0>();
        }
        __syncthreads();
        warp_mma64t<VSTH>(Apb[t & 1], Bpb[t & 1], acc, wy, wx, lane);
        __syncthreads();
    }

    const int tg = lane & 3, rr = lane >> 2;
#pragma unroll
    for (int mf = 0; mf < 2; mf++) {
        int m = m0 + wy * 32 + mf * 16 + rr;
#pragma unroll
        for (int nf = 0; nf < 8; nf++) {
            int n = n0 + wx * 64 + nf * 8 + tg * 2;
            *(uint32_t*)(P + (size_t)m * N + n) = pack2(acc[mf][nf][0], acc[mf][nf][1]);
            *(uint32_t*)(P + (size_t)(m + 8) * N + n) = pack2(acc[mf][nf][2], acc[mf][nf][3]);
        }
    }
}

// ---------------------------------------------------------------------------
// Kernel 2: g_invDh[z][c2] = half(1 / sum_q exp(S/8)).  f16x2 ex2 path.
// ---------------------------------------------------------------------------
__global__ __launch_bounds__(256, 2) void k_sums() {
    __half* As = dsm;
    __half* Bs[2] = {dsm + TILEH, dsm + 2 * TILEH};
    float* sD = (float*)(dsm + 3 * TILEH);
    const int tid = threadIdx.x, lane = tid & 31, wid = tid >> 5;
    const int wy = wid & 3, wx = wid >> 2;
    const int tg = lane & 3, rr = lane >> 2;
    const int z = blockIdx.y;
    const int c20 = blockIdx.x * 128;
    const __half* Kh = g_Pk + (size_t)z * Cc * Kk;
    const __half* Qh = g_Pq + (size_t)z * Cc * Kk;

    if (tid < 128) sD[tid] = 0.f;

#pragma unroll
    for (int p = 0; p < 4; p++) {
        int id = tid + 256 * p, r = id >> 3, c = id & 7;
        cpa16(s2u(As + r * STH + c * 8), Kh + (size_t)(c20 + r) * Kk + c * 8);
        cpa16(s2u(Bs[0] + r * STH + c * 8), Qh + (size_t)r * Kk + c * 8);
    }
    cp_commit();

    float rs[2][2] = {{0.f, 0.f}, {0.f, 0.f}};
    const int NT = Cc / 128;
    for (int t = 0; t < NT; t++) {
        __syncthreads();
        if (t + 1 < NT) {
            const __half* src = Qh + (size_t)(t + 1) * 128 * Kk;
            __half* dst = Bs[(t + 1) & 1];
#pragma unroll
            for (int p = 0; p < 4; p++) {
                int id = tid + 256 * p, r = id >> 3, c = id & 7;
                cpa16(s2u(dst + r * STH + c * 8), src + (size_t)r * Kk + c * 8);
            }
            cp_commit();
            cp_wait<1>();
        } else {
            cp_wait<0>();
        }
        __syncthreads();

        float acc[2][8][4];
#pragma unroll
        for (int i = 0; i < 2; i++)
#pragma unroll
            for (int j = 0; j < 8; j++)
#pragma unroll
                for (int c = 0; c < 4; c++) acc[i][j][c] = 0.f;
        warp_mma64<STH>(As, Bs[t & 1], acc, wy, wx, lane);
#pragma unroll
        for (int mf = 0; mf < 2; mf++)
#pragma unroll
            for (int nf = 0; nf < 8; nf++) {
                uint32_t e0 = ex2h2(pack2(acc[mf][nf][0] * KE, acc[mf][nf][1] * KE));
                uint32_t e1 = ex2h2(pack2(acc[mf][nf][2] * KE, acc[mf][nf][3] * KE));
                float2 f0 = __half22float2(*(__half2*)&e0);
                float2 f1 = __half22float2(*(__half2*)&e1);
                rs[mf][0] += f0.x + f0.y;
                rs[mf][1] += f1.x + f1.y;
            }
    }
#pragma unroll
    for (int mf = 0; mf < 2; mf++)
#pragma unroll
        for (int h2 = 0; h2 < 2; h2++) {
            float s = rs[mf][h2];
            s += __shfl_xor_sync(0xffffffffu, s, 1);
            s += __shfl_xor_sync(0xffffffffu, s, 2);
            if (tg == 0)
                atomicAdd(&sD[wy * 32 + mf * 16 + h2 * 8 + rr], s);
        }
    __syncthreads();
    if (tid < 128)
        g_invDh[z * Cc + c20 + tid] = __float2half_rn(1.0f / sD[tid]);
}

// ---------------------------------------------------------------------------
// Kernel 3: fused scores+softmax+PV.  Per-j interleave (16 c2 granularity):
// GEMM1(j) -> exp -> GEMM2(kb=j).  Cuts peak live regs to kill spills.
// ---------------------------------------------------------------------------
__global__ __launch_bounds__(256, 1) void k_fused(float* __restrict__ out) {
    __half* Ks[2] = {dsm, dsm + TILEH};
    __half* Vs[2] = {dsm + 2 * TILEH, dsm + 2 * TILEH + VTILEH};
    __half* iDbase = dsm + 2 * TILEH + 2 * VTILEH;
    __half* iDs[2] = {iDbase, iDbase + 128};
    const int tid = threadIdx.x, lane = tid & 31, wid = tid >> 5;
    const int tg = lane & 3, rr = lane >> 2;
    const int w = blockIdx.x;
    const int b = w >> 6, h = (w >> 3) & 7, hp = w & 7, z = w >> 3;
    const __half* Qh = g_Pq + (size_t)z * Cc * Kk;
    const __half* Kh = g_Pk + (size_t)z * Cc * Kk;
    const __half* Bv = g_Pv + (size_t)b * Cc * HV + (size_t)hp * Uu * HV;
    const __half* iDh = g_invDh + z * Cc;

    const int u1b = wid * 32 + rr;
    const __half* Qbase = Qh + (size_t)(8 * u1b + hp) * Kk;
    uint32_t Qa[2][4][4];
#pragma unroll
    for (int mf = 0; mf < 2; mf++) {
        const __half* Q0 = Qbase + (size_t)(mf * 128) * Kk;
        const __half* Q1 = Q0 + (size_t)64 * Kk;
#pragma unroll
        for (int ks = 0; ks < 4; ks++) {
            Qa[mf][ks][0] = *(const uint32_t*)(Q0 + ks * 16 + 2 * tg);
            Qa[mf][ks][1] = *(const uint32_t*)(Q1 + ks * 16 + 2 * tg);
            Qa[mf][ks][2] = *(const uint32_t*)(Q0 + ks * 16 + 8 + 2 * tg);
            Qa[mf][ks][3] = *(const uint32_t*)(Q1 + ks * 16 + 8 + 2 * tg);
        }
    }

    float of[2][16][4];
#pragma unroll
    for (int mf = 0; mf < 2; mf++)
#pragma unroll
        for (int j = 0; j < 16; j++)
#pragma unroll
            for (int c = 0; c < 4; c++) of[mf][j][c] = 0.f;

    auto fill = [&](int c20, __half* ks, __half* vs, __half* ids) {
#pragma unroll
        for (int p = 0; p < 4; p++) {
            int id = tid + 256 * p, r = id >> 3, c = id & 7;
            cpa16(s2u(ks + r * STH + c * 8), Kh + (size_t)(c20 + r) * Kk + c * 8);
        }
#pragma unroll
        for (int p = 0; p < 8; p++) {
            int id = tid + 256 * p, r = id >> 4, c = id & 15;
            cpa16(s2u(vs + r * VSTH + c * 8), Bv + (size_t)(c20 + r) * Vd + c * 8);
        }
        if (tid < 16) cpa16(s2u(ids + tid * 8), iDh + c20 + tid * 8);
    };

    fill(0, Ks[0], Vs[0], iDs[0]);
    cp_commit();

    const int brow = (lane & 7) + ((lane >> 4) << 3);
    const int kB = ((lane >> 3) & 1) << 3;
    const int vkrow = (lane & 7) + (((lane >> 3) & 1) << 3);
    const int vcol = (lane >> 4) << 3;

    const int NT = Cc / 128;
    for (int t = 0; t < NT; t++) {
        __syncthreads();
        if (t + 1 < NT) {
            fill((t + 1) * 128, Ks[(t + 1) & 1], Vs[(t + 1) & 1], iDs[(t + 1) & 1]);
            cp_commit();
            cp_wait<1>();
        } else {
            cp_wait<0>();
        }
        __syncthreads();

        const uint32_t ksb = s2u(Ks[t & 1]), vsb = s2u(Vs[t & 1]);
        const __half* ids = iDs[t & 1];

#pragma unroll
        for (int j = 0; j < 8; j++) {
            // GEMM1 for c2 group [j*16, j*16+16): cf[mf][nhalf][4]
            float cf[2][2][4];
#pragma unroll
            for (int mf = 0; mf < 2; mf++)
#pragma unroll
                for (int n = 0; n < 2; n++)
#pragma unroll
                    for (int c = 0; c < 4; c++) cf[mf][n][c] = 0.f;
#pragma unroll
            for (int ks = 0; ks < 4; ks++) {
                uint32_t bfr[4];
                ldm4(bfr, ksb + (uint32_t)(((j * 16 + brow) * STH + ks * 16 + kB) * 2));
                mma16(cf[0][0], Qa[0][ks], bfr);
                mma16(cf[0][1], Qa[0][ks], bfr + 2);
                mma16(cf[1][0], Qa[1][ks], bfr);
                mma16(cf[1][1], Qa[1][ks], bfr + 2);
            }

            // exp * invD -> one A-fragment (k=16) per mf
            uint32_t ak[2][4];
#pragma unroll
            for (int mf = 0; mf < 2; mf++)
#pragma unroll
                for (int nh = 0; nh < 2; nh++) {
                    int nfg = j * 2 + nh;
                    uint32_t idh = *(const uint32_t*)(ids + nfg * 8 + 2 * tg);
                    uint32_t e0 = ex2h2(pack2(cf[mf][nh][0] * KE, cf[mf][nh][1] * KE));
                    uint32_t e1 = ex2h2(pack2(cf[mf][nh][2] * KE, cf[mf][nh][3] * KE));
                    ak[mf][nh * 2 + 0] = hmul2(e0, idh);
                    ak[mf][nh * 2 + 1] = hmul2(e1, idh);
                }

            // GEMM2 partial: kb = j, full d (8 output column groups)
#pragma unroll
            for (int j2 = 0; j2 < 8; j2++) {
                uint32_t bfr[4];
                ldm4t(bfr, vsb + (uint32_t)(((j * 16 + vkrow) * VSTH + j2 * 16 + vcol) * 2));
                mma16(of[0][2 * j2], ak[0], bfr);
                mma16(of[0][2 * j2 + 1], ak[0], bfr + 2);
                mma16(of[1][2 * j2], ak[1], bfr);
                mma16(of[1][2 * j2 + 1], ak[1], bfr + 2);
            }
        }
    }

#pragma unroll
    for (int mf = 0; mf < 2; mf++) {
        int u1 = wid * 32 + mf * 16 + rr;
        float* g0 = out + ((size_t)b * Cc + h * Uu + u1) * HV + hp * Vd;
        float* g1 = g0 + (size_t)8 * HV;
#pragma unroll
        for (int df = 0; df < 16; df++) {
            int d = df * 8 + 2 * tg;
            *(float2*)(g0 + d) = make_float2(of[mf][df][0], of[mf][df][1]);
            *(float2*)(g1 + d) = make_float2(of[mf][df][2], of[mf][df][3]);
        }
    }
}

// ---------------------------------------------------------------------------
extern "C" void kernel_launch(void* const* d_in, const int* in_sizes, int n_in,
                              void* d_out, int out_size) {
    (void)in_sizes; (void)n_in; (void)out_size;
    const float* x  = (const float*)d_in[0];
    const float* Mq = (const float*)d_in[1];
    const float* Mk = (const float*)d_in[2];
    const float* Mv = (const float*)d_in[3];
    float* out = (float*)d_out;

    __half *pXh, *pWq, *pWk, *pWv, *pPq, *pPk, *pPv;
    cudaGetSymbolAddress((void**)&pXh, g_Xh);
    cudaGetSymbolAddress((void**)&pWq, g_Wq);
    cudaGetSymbolAddress((void**)&pWk, g_Wk);
    cudaGetSymbolAddress((void**)&pWv, g_Wv);
    cudaGetSymbolAddress((void**)&pPq, g_Pq);
    cudaGetSymbolAddress((void**)&pPk, g_Pk);
    cudaGetSymbolAddress((void**)&pPv, g_Pv);

    const int DSMP = (2 * TILEH + 2 * BTILEH) * sizeof(__half);          // 71680
    const int DSMS = 3 * TILEH * sizeof(__half) + 512;                   // 55808
    const int DSMF = (2 * TILEH + 2 * VTILEH) * sizeof(__half) + 1024;   // 107520
    static bool attr_done = false;
    if (!attr_done) {
        cudaFuncSetAttribute(k_proj3, cudaFuncAttributeMaxDynamicSharedMemorySize, DSMP);
        cudaFuncSetAttribute(k_sums, cudaFuncAttributeMaxDynamicSharedMemorySize, DSMS);
        cudaFuncSetAttribute(k_fused, cudaFuncAttributeMaxDynamicSharedMemorySize, DSMF);
        attr_done = true;
    }

    k_cvt_all<<<5120, 256>>>(x, Mq, Mk, Mv, pXh, pWq, pWk, pWv);
    k_proj3<<<dim3(16, (Bb * Cc) / 128), 256, DSMP>>>(pXh, pWq, pWk, pWv,
                                                      pPq, pPk, pPv);
    k_sums<<<dim3(Cc / 128, Bb * 8), 256, DSMS>>>();
    k_fused<<<Bb * 8 * 8, 256, DSMF>>>(out);
}